// round 1
// baseline (speedup 1.0000x reference)
#include <cuda_runtime.h>
#include <cstdint>
#include <cstddef>

// ---------------------------------------------------------------------------
// Problem constants
// ---------------------------------------------------------------------------
#define BB    32
#define CIN   128
#define COUT  256
#define HH    32
#define WW    32
#define HWP   1024              // H*W
#define MROWS 32768             // B*H*W
#define MEMN  64
#define EPSBN 1e-5f

// ---------------------------------------------------------------------------
// Scratch: one big __device__ array, offsets in floats (no allocations!)
// ---------------------------------------------------------------------------
#define OFF_COL    0ull                     // 32768*2304        = 75497472
#define OFF_XN     75497472ull              // 32768*128         =  4194304
#define OFF_T1     79691776ull              // 32768*256
#define OFF_T2     88080384ull
#define OFF_XF     96468992ull
#define OFF_RETR   104857600ull
#define OFF_GATE   113246208ull
#define OFF_SCV    121634816ull
#define OFF_L      130023424ull             // 32768*64 = 2097152
#define OFF_W1R    132120576ull             // 256*1152 = 294912
#define OFF_W2R    132415488ull             // 256*2304 = 589824
#define OFF_PSUM   133005312ull             // 256*256
#define OFF_PSQ    133070848ull
#define OFF_PAVG   133136384ull             // 256*256
#define OFF_PMAX   133201920ull
#define OFF_CATT   133267456ull             // 32*256
#define OFF_SPM    133275648ull             // 32768
#define OFF_SPX    133308416ull
#define OFF_SA     133341184ull
#define OFF_BN1SC  133373952ull             // 256 each below
#define OFF_BN1SH  133374208ull
#define OFF_BN2SC  133374464ull
#define OFF_BN2SH  133374720ull
#define OFF_SCSC   133374976ull
#define OFF_SCSH   133375232ull
#define SCRATCH_TOTAL 133375488ull

__device__ float g_scratch[SCRATCH_TOTAL];

// ---------------------------------------------------------------------------
// NCHW -> NHWC transpose (for x, C=128)
// grid (B*(HW/32), C/32), block (32,8)
// ---------------------------------------------------------------------------
__global__ void k_nchw_to_nhwc(const float* __restrict__ src, float* __restrict__ dst, int C)
{
    __shared__ float tile[32][33];
    int b  = blockIdx.x >> 5;
    int p0 = (blockIdx.x & 31) << 5;
    int c0 = blockIdx.y << 5;
    for (int i = threadIdx.y; i < 32; i += 8)
        tile[i][threadIdx.x] = src[((size_t)b * C + c0 + i) * HWP + p0 + threadIdx.x];
    __syncthreads();
    for (int i = threadIdx.y; i < 32; i += 8)
        dst[((size_t)(b << 10) + p0 + i) * C + c0 + threadIdx.x] = tile[threadIdx.x][i];
}

// ---------------------------------------------------------------------------
// Weight reorder: w[n][ic][tap] -> wr[n][tap*Cin + ic]   (tap-major K)
// ---------------------------------------------------------------------------
__global__ void k_reorder_w(const float* __restrict__ w, float* __restrict__ wr, int Cin)
{
    int idx = blockIdx.x * 256 + threadIdx.x;
    int total = COUT * Cin * 9;
    if (idx >= total) return;
    int n   = idx / (Cin * 9);
    int rem = idx - n * (Cin * 9);
    int ic  = rem / 9;
    int tap = rem - ic * 9;
    wr[(size_t)n * Cin * 9 + tap * Cin + ic] = w[idx];
}

// ---------------------------------------------------------------------------
// im2col for 3x3 pad 1, tap-major K order. Optional fused BN(scale/shift)+ReLU.
// c4shift: log2(C/4). idx covers MROWS*9*(C/4) float4s.
// ---------------------------------------------------------------------------
__global__ void k_im2col3x3(const float* __restrict__ src, float* __restrict__ col,
                            int C, int c4shift,
                            const float* __restrict__ scale, const float* __restrict__ shift)
{
    int idx = blockIdx.x * 256 + threadIdx.x;
    int cc  = idx & ((1 << c4shift) - 1);
    int r   = idx >> c4shift;
    int m   = r / 9;
    int tap = r - m * 9;
    if (m >= MROWS) return;
    int b = m >> 10, p = m & 1023, y = p >> 5, xp = p & 31;
    int dy = tap / 3 - 1, dx = tap - (tap / 3) * 3 - 1;
    int yy = y + dy, xx = xp + dx;
    float4 v = make_float4(0.f, 0.f, 0.f, 0.f);
    if ((unsigned)yy < 32u && (unsigned)xx < 32u) {
        v = *(const float4*)(src + ((size_t)((b << 10) + (yy << 5) + xx)) * C + (cc << 2));
        if (scale) {
            float4 sc = *(const float4*)(scale + (cc << 2));
            float4 sh = *(const float4*)(shift + (cc << 2));
            v.x = fmaxf(v.x * sc.x + sh.x, 0.f);
            v.y = fmaxf(v.y * sc.y + sh.y, 0.f);
            v.z = fmaxf(v.z * sc.z + sh.z, 0.f);
            v.w = fmaxf(v.w * sc.w + sh.w, 0.f);
        }
    }
    *(float4*)(col + (size_t)m * (9 * C) + tap * C + (cc << 2)) = v;
}

// ---------------------------------------------------------------------------
// SGEMM: C[M,N] = alpha * A[M,K] * W[N,K]^T (+ C) (+ bias) (relu/sigmoid)
// BM=128, BN=64, BK=16, 256 threads, 8x4 micro-tile.
// Requires M%128==0, N%64==0, K%16==0 (all shapes here satisfy this).
// ---------------------------------------------------------------------------
#define F_BIAS 1
#define F_RELU 2
#define F_ACC  4
#define F_SIG  8

__global__ void __launch_bounds__(256, 4)
k_sgemm(const float* __restrict__ A, const float* __restrict__ Wt,
        float* __restrict__ C, const float* __restrict__ bias,
        int Mtot, int N, int K, int ldw, float alpha, int flags)
{
    __shared__ float As[16][128];
    __shared__ float Ws[16][64];
    int tid = threadIdx.x;
    int bm = blockIdx.x * 128;
    int bn = blockIdx.y * 64;
    int tx = tid & 15, ty = tid >> 4;
    float acc[8][4] = {};

    for (int k0 = 0; k0 < K; k0 += 16) {
#pragma unroll
        for (int i = 0; i < 2; i++) {
            int idx = tid * 2 + i;
            int ar = idx >> 2, ac = (idx & 3) << 2;
            float4 v = *(const float4*)(A + (size_t)(bm + ar) * K + k0 + ac);
            As[ac + 0][ar] = v.x; As[ac + 1][ar] = v.y;
            As[ac + 2][ar] = v.z; As[ac + 3][ar] = v.w;
        }
        {
            int wr = tid >> 2, wc = (tid & 3) << 2;
            float4 v = *(const float4*)(Wt + (size_t)(bn + wr) * ldw + k0 + wc);
            Ws[wc + 0][wr] = v.x; Ws[wc + 1][wr] = v.y;
            Ws[wc + 2][wr] = v.z; Ws[wc + 3][wr] = v.w;
        }
        __syncthreads();
#pragma unroll
        for (int kk = 0; kk < 16; kk++) {
            float4 a0 = *(const float4*)(&As[kk][ty * 8]);
            float4 a1 = *(const float4*)(&As[kk][ty * 8 + 4]);
            float4 w0 = *(const float4*)(&Ws[kk][tx * 4]);
            float a[8] = {a0.x, a0.y, a0.z, a0.w, a1.x, a1.y, a1.z, a1.w};
            float w[4] = {w0.x, w0.y, w0.z, w0.w};
#pragma unroll
            for (int i = 0; i < 8; i++)
#pragma unroll
                for (int j = 0; j < 4; j++)
                    acc[i][j] += a[i] * w[j];
        }
        __syncthreads();
    }

#pragma unroll
    for (int i = 0; i < 8; i++) {
        int row = bm + ty * 8 + i;
#pragma unroll
        for (int j = 0; j < 4; j++) {
            int col = bn + tx * 4 + j;
            float v = acc[i][j] * alpha;
            size_t id = (size_t)row * N + col;
            if (flags & F_ACC)  v += C[id];
            if (flags & F_BIAS) v += bias[col];
            if (flags & F_RELU) v = fmaxf(v, 0.f);
            if (flags & F_SIG)  v = 1.f / (1.f + expf(-v));
            C[id] = v;
        }
    }
}

// ---------------------------------------------------------------------------
// Deterministic BN stats (two stage) over M=32768 rows x 256 channels (NHWC)
// ---------------------------------------------------------------------------
__global__ void k_bn_partial(const float* __restrict__ t, float* __restrict__ psum,
                             float* __restrict__ psq)
{
    int c = threadIdx.x;
    int r0 = blockIdx.x * 128;
    float s = 0.f, s2 = 0.f;
    for (int r = 0; r < 128; r++) {
        float v = t[(size_t)(r0 + r) * 256 + c];
        s += v; s2 += v * v;
    }
    psum[blockIdx.x * 256 + c] = s;
    psq [blockIdx.x * 256 + c] = s2;
}

__global__ void k_bn_finalize(const float* __restrict__ psum, const float* __restrict__ psq,
                              const float* __restrict__ gamma, const float* __restrict__ beta,
                              float* __restrict__ scale, float* __restrict__ shift)
{
    int c = threadIdx.x;
    float s = 0.f, s2 = 0.f;
    for (int i = 0; i < 256; i++) { s += psum[i * 256 + c]; s2 += psq[i * 256 + c]; }
    float mean = s / 32768.f;
    float var  = s2 / 32768.f - mean * mean;
    float sc   = gamma[c] * rsqrtf(var + EPSBN);
    scale[c] = sc;
    shift[c] = beta[c] - mean * sc;
}

__global__ void k_bn_apply(float* __restrict__ t, const float* __restrict__ scale,
                           const float* __restrict__ shift)
{
    int idx = blockIdx.x * 256 + threadIdx.x;   // MROWS*64 float4s
    int c4 = idx & 63;
    float4 v  = ((float4*)t)[idx];
    float4 sc = ((const float4*)scale)[c4];
    float4 sh = ((const float4*)shift)[c4];
    v.x = v.x * sc.x + sh.x; v.y = v.y * sc.y + sh.y;
    v.z = v.z * sc.z + sh.z; v.w = v.w * sc.w + sh.w;
    ((float4*)t)[idx] = v;
}

// ---------------------------------------------------------------------------
// Channel attention: pooling partials (grid 32*8, block 256=channel)
// ---------------------------------------------------------------------------
__global__ void k_ca_pool_partial(const float* __restrict__ t2, float* __restrict__ pavg,
                                  float* __restrict__ pmax)
{
    int b = blockIdx.x >> 3, ch = blockIdx.x & 7;
    int c = threadIdx.x;
    float s = 0.f, mx = -1e30f;
    for (int p = 0; p < 128; p++) {
        float v = t2[((size_t)(b << 10) + (ch << 7) + p) * 256 + c];
        s += v; mx = fmaxf(mx, v);
    }
    pavg[blockIdx.x * 256 + c] = s;
    pmax[blockIdx.x * 256 + c] = mx;
}

// CA MLP: grid 32 (batch), 256 threads
__global__ void k_ca_mlp(const float* __restrict__ pavg, const float* __restrict__ pmax,
                         const float* __restrict__ w1, const float* __restrict__ w2,
                         float* __restrict__ catt)
{
    __shared__ float av[256], mx[256], h[32];
    int b = blockIdx.x, c = threadIdx.x;
    float s = 0.f, m = -1e30f;
    for (int i = 0; i < 8; i++) {
        s += pavg[(b * 8 + i) * 256 + c];
        m = fmaxf(m, pmax[(b * 8 + i) * 256 + c]);
    }
    av[c] = s / 1024.f; mx[c] = m;
    __syncthreads();
    if (c < 32) {
        const float* src = (c < 16) ? av : mx;
        int j = c & 15;
        float acc = 0.f;
        for (int k = 0; k < 256; k++) acc += w1[j * 256 + k] * src[k];
        h[c] = fmaxf(acc, 0.f);
    }
    __syncthreads();
    float acc = 0.f;
#pragma unroll
    for (int j = 0; j < 16; j++) acc += w2[c * 16 + j] * (h[j] + h[16 + j]);
    catt[b * 256 + c] = 1.f / (1.f + expf(-acc));
}

// ---------------------------------------------------------------------------
// Spatial pooling (after channel attn): warp per pixel. grid 4096, block 256.
// ---------------------------------------------------------------------------
__global__ void k_sp_pool(const float* __restrict__ t2, const float* __restrict__ catt,
                          float* __restrict__ spm, float* __restrict__ spx)
{
    int warp = threadIdx.x >> 5, lane = threadIdx.x & 31;
    int m = blockIdx.x * 8 + warp;
    int b = m >> 10;
    float s = 0.f, mx = -1e30f;
#pragma unroll
    for (int i = 0; i < 8; i++) {
        int c = i * 32 + lane;
        float v = t2[(size_t)m * 256 + c] * catt[b * 256 + c];
        s += v; mx = fmaxf(mx, v);
    }
    for (int o = 16; o; o >>= 1) {
        s += __shfl_xor_sync(0xffffffffu, s, o);
        mx = fmaxf(mx, __shfl_xor_sync(0xffffffffu, mx, o));
    }
    if (lane == 0) { spm[m] = s / 256.f; spx[m] = mx; }
}

// Spatial 7x7 conv (2ch -> 1) + sigmoid. grid 32 (batch), block 256.
__global__ void k_sa_conv(const float* __restrict__ spm, const float* __restrict__ spx,
                          const float* __restrict__ saw, const float* __restrict__ sab,
                          float* __restrict__ sa)
{
    __shared__ float sm[1024], sx[1024], w[98];
    int b = blockIdx.x, t = threadIdx.x;
    for (int i = t; i < 1024; i += 256) { sm[i] = spm[b * 1024 + i]; sx[i] = spx[b * 1024 + i]; }
    if (t < 98) w[t] = saw[t];
    __syncthreads();
    float bias = sab[0];
    for (int i = t; i < 1024; i += 256) {
        int y = i >> 5, x = i & 31;
        float acc = bias;
#pragma unroll
        for (int ky = 0; ky < 7; ky++) {
            int yy = y + ky - 3; if ((unsigned)yy >= 32u) continue;
#pragma unroll
            for (int kx = 0; kx < 7; kx++) {
                int xx = x + kx - 3; if ((unsigned)xx >= 32u) continue;
                acc += w[ky * 7 + kx] * sm[yy * 32 + xx] + w[49 + ky * 7 + kx] * sx[yy * 32 + xx];
            }
        }
        sa[b * 1024 + i] = 1.f / (1.f + expf(-acc));
    }
}

// xf = t2 * catt * sa   (float4 over c)
__global__ void k_apply_att(const float* __restrict__ t2, const float* __restrict__ catt,
                            const float* __restrict__ sa, float* __restrict__ xf)
{
    int idx = blockIdx.x * 256 + threadIdx.x;   // MROWS*64
    int m = idx >> 6, c4 = idx & 63;
    int b = m >> 10;
    float s = sa[m];
    float4 v  = ((const float4*)t2)[idx];
    float4 ca = ((const float4*)(catt + b * 256))[c4];
    v.x *= ca.x * s; v.y *= ca.y * s; v.z *= ca.z * s; v.w *= ca.w * s;
    ((float4*)xf)[idx] = v;
}

// ---------------------------------------------------------------------------
// Fused softmax over 64 logits + retrieved = attn @ mem. Warp per row.
// Dynamic smem: 64x256 floats (64KB) of mem.
// ---------------------------------------------------------------------------
__global__ void k_softmax_retrieve(const float* __restrict__ L, const float* __restrict__ mem,
                                   float* __restrict__ retr)
{
    extern __shared__ float ms[];
    for (int i = threadIdx.x; i < 16384; i += 256) ms[i] = mem[i];
    __syncthreads();
    int warp = threadIdx.x >> 5, lane = threadIdx.x & 31;
    int m = blockIdx.x * 8 + warp;
    float l0 = L[(size_t)m * 64 + lane];
    float l1 = L[(size_t)m * 64 + 32 + lane];
    float mx = fmaxf(l0, l1);
    for (int o = 16; o; o >>= 1) mx = fmaxf(mx, __shfl_xor_sync(0xffffffffu, mx, o));
    float e0 = expf(l0 - mx), e1 = expf(l1 - mx);
    float s = e0 + e1;
    for (int o = 16; o; o >>= 1) s += __shfl_xor_sync(0xffffffffu, s, o);
    float inv = 1.f / s;
    e0 *= inv; e1 *= inv;
    float acc[8] = {};
    for (int j = 0; j < 32; j++) {
        float a0 = __shfl_sync(0xffffffffu, e0, j);
        float a1 = __shfl_sync(0xffffffffu, e1, j);
#pragma unroll
        for (int f = 0; f < 8; f++)
            acc[f] += a0 * ms[j * 256 + f * 32 + lane] + a1 * ms[(j + 32) * 256 + f * 32 + lane];
    }
#pragma unroll
    for (int f = 0; f < 8; f++) retr[(size_t)m * 256 + f * 32 + lane] = acc[f];
}

// ---------------------------------------------------------------------------
// Final: mo = g*retr+(1-g)*xf; spike = (0.1*mo>=1); out = relu(spike + BN(scv))
// with NHWC -> NCHW transpose. grid (B*32, 8), block (32,8).
// ---------------------------------------------------------------------------
__global__ void k_final(const float* __restrict__ g, const float* __restrict__ retr,
                        const float* __restrict__ xf, const float* __restrict__ scv,
                        const float* __restrict__ scScale, const float* __restrict__ scShift,
                        float* __restrict__ out)
{
    __shared__ float tile[32][33];
    int b = blockIdx.x >> 5, p0 = (blockIdx.x & 31) << 5, c0 = blockIdx.y << 5;
    int tx = threadIdx.x, ty = threadIdx.y;
    for (int i = ty; i < 32; i += 8) {
        int m = (b << 10) + p0 + i;
        int c = c0 + tx;
        size_t id = (size_t)m * 256 + c;
        float gg = g[id], rr = retr[id], xx = xf[id];
        float mo = gg * rr + (1.f - gg) * xx;
        float spike = (0.1f * mo >= 1.f) ? 1.f : 0.f;
        float idn = scv[id] * scScale[c] + scShift[c];
        tile[tx][i] = fmaxf(spike + idn, 0.f);
    }
    __syncthreads();
    for (int i = ty; i < 32; i += 8)
        out[((size_t)b * 256 + c0 + i) * HWP + p0 + tx] = tile[i][tx];
}

// ---------------------------------------------------------------------------
// Launch
// ---------------------------------------------------------------------------
extern "C" void kernel_launch(void* const* d_in, const int* in_sizes, int n_in,
                              void* d_out, int out_size)
{
    const float* x        = (const float*)d_in[0];
    const float* conv1_w  = (const float*)d_in[1];
    const float* conv1_b  = (const float*)d_in[2];
    const float* bn1_g    = (const float*)d_in[3];
    const float* bn1_b    = (const float*)d_in[4];
    const float* conv2_w  = (const float*)d_in[5];
    const float* conv2_b  = (const float*)d_in[6];
    const float* bn2_g    = (const float*)d_in[7];
    const float* bn2_b    = (const float*)d_in[8];
    const float* ca_w1    = (const float*)d_in[9];
    const float* ca_w2    = (const float*)d_in[10];
    const float* sa_w     = (const float*)d_in[11];
    const float* sa_b     = (const float*)d_in[12];
    const float* memv     = (const float*)d_in[13];
    const float* mem_keys = (const float*)d_in[14];
    const float* ctrl_w1  = (const float*)d_in[15];
    const float* ctrl_b1  = (const float*)d_in[16];
    const float* ctrl_w2  = (const float*)d_in[17];
    const float* ctrl_b2  = (const float*)d_in[18];
    const float* gate_w   = (const float*)d_in[19];
    const float* gate_b   = (const float*)d_in[20];
    const float* sc_w     = (const float*)d_in[21];
    const float* sc_g     = (const float*)d_in[22];
    const float* sc_b     = (const float*)d_in[23];
    float* out = (float*)d_out;

    void* basep = nullptr;
    cudaGetSymbolAddress(&basep, g_scratch);
    float* S = (float*)basep;

    float* col   = S + OFF_COL;
    float* xn    = S + OFF_XN;
    float* t1    = S + OFF_T1;     // conv1 out; later reused as MLP hidden h1
    float* t2    = S + OFF_T2;     // conv2/bn2 out; later reused as q
    float* xf    = S + OFF_XF;
    float* retr  = S + OFF_RETR;
    float* gate  = S + OFF_GATE;
    float* scv   = S + OFF_SCV;
    float* Lbuf  = S + OFF_L;
    float* w1r   = S + OFF_W1R;
    float* w2r   = S + OFF_W2R;
    float* psum  = S + OFF_PSUM;
    float* psq   = S + OFF_PSQ;
    float* pavg  = S + OFF_PAVG;
    float* pmax  = S + OFF_PMAX;
    float* catt  = S + OFF_CATT;
    float* spm   = S + OFF_SPM;
    float* spx   = S + OFF_SPX;
    float* sa    = S + OFF_SA;
    float* bn1sc = S + OFF_BN1SC;  float* bn1sh = S + OFF_BN1SH;
    float* bn2sc = S + OFF_BN2SC;  float* bn2sh = S + OFF_BN2SH;
    float* scsc  = S + OFF_SCSC;   float* scsh  = S + OFF_SCSH;

    cudaFuncSetAttribute(k_softmax_retrieve, cudaFuncAttributeMaxDynamicSharedMemorySize, 65536);

    dim3 tb32x8(32, 8);

    // 1) x -> NHWC
    k_nchw_to_nhwc<<<dim3(BB * 32, CIN / 32), tb32x8>>>(x, xn, CIN);

    // 2) weight reorders
    k_reorder_w<<<(COUT * CIN * 9 + 255) / 256, 256>>>(conv1_w, w1r, CIN);
    k_reorder_w<<<(COUT * COUT * 9 + 255) / 256, 256>>>(conv2_w, w2r, COUT);

    // 3) conv1 = im2col + GEMM (+bias)
    k_im2col3x3<<<MROWS * 9 * (CIN / 4) / 256, 256>>>(xn, col, CIN, 5, nullptr, nullptr);
    k_sgemm<<<dim3(MROWS / 128, COUT / 64), 256>>>(col, w1r, t1, conv1_b,
                                                   MROWS, COUT, 9 * CIN, 9 * CIN, 1.f, F_BIAS);

    // 4) BN1 stats (apply fused into im2col2)
    k_bn_partial<<<256, 256>>>(t1, psum, psq);
    k_bn_finalize<<<1, 256>>>(psum, psq, bn1_g, bn1_b, bn1sc, bn1sh);

    // 5) conv2 = im2col(BN1+ReLU fused) + GEMM (+bias)
    k_im2col3x3<<<MROWS * 9 * (COUT / 4) / 256, 256>>>(t1, col, COUT, 6, bn1sc, bn1sh);
    k_sgemm<<<dim3(MROWS / 128, COUT / 64), 256>>>(col, w2r, t2, conv2_b,
                                                   MROWS, COUT, 9 * COUT, 9 * COUT, 1.f, F_BIAS);

    // 6) BN2 stats + apply in place
    k_bn_partial<<<256, 256>>>(t2, psum, psq);
    k_bn_finalize<<<1, 256>>>(psum, psq, bn2_g, bn2_b, bn2sc, bn2sh);
    k_bn_apply<<<MROWS * 64 / 256, 256>>>(t2, bn2sc, bn2sh);

    // 7) channel attention
    k_ca_pool_partial<<<BB * 8, 256>>>(t2, pavg, pmax);
    k_ca_mlp<<<BB, 256>>>(pavg, pmax, ca_w1, ca_w2, catt);

    // 8) spatial attention
    k_sp_pool<<<MROWS / 8, 256>>>(t2, catt, spm, spx);
    k_sa_conv<<<BB, 256>>>(spm, spx, sa_w, sa_b, sa);
    k_apply_att<<<MROWS * 64 / 256, 256>>>(t2, catt, sa, xf);

    // 9) memory module
    //   h1 = relu(xf @ ctrl_w1^T + b1)   (into t1)
    k_sgemm<<<dim3(MROWS / 128, COUT / 64), 256>>>(xf, ctrl_w1, t1, ctrl_b1,
                                                   MROWS, COUT, COUT, COUT, 1.f, F_BIAS | F_RELU);
    //   q = h1 @ ctrl_w2^T + b2          (into t2)
    k_sgemm<<<dim3(MROWS / 128, COUT / 64), 256>>>(t1, ctrl_w2, t2, ctrl_b2,
                                                   MROWS, COUT, COUT, COUT, 1.f, F_BIAS);
    //   logits = q @ mem_keys^T / 16
    k_sgemm<<<dim3(MROWS / 128, 1), 256>>>(t2, mem_keys, Lbuf, nullptr,
                                           MROWS, MEMN, COUT, COUT, 1.f / 16.f, 0);
    //   softmax + retrieved
    k_softmax_retrieve<<<MROWS / 8, 256, 65536>>>(Lbuf, memv, retr);
    //   gate = sigmoid(xf @ Gx^T + retr @ Gr^T + gb)
    k_sgemm<<<dim3(MROWS / 128, COUT / 64), 256>>>(xf, gate_w, gate, nullptr,
                                                   MROWS, COUT, COUT, 2 * COUT, 1.f, 0);
    k_sgemm<<<dim3(MROWS / 128, COUT / 64), 256>>>(retr, gate_w + COUT, gate, gate_b,
                                                   MROWS, COUT, COUT, 2 * COUT, 1.f,
                                                   F_ACC | F_BIAS | F_SIG);

    // 10) shortcut: 1x1 conv (GEMM) + BN stats
    k_sgemm<<<dim3(MROWS / 128, COUT / 64), 256>>>(xn, sc_w, scv, nullptr,
                                                   MROWS, COUT, CIN, CIN, 1.f, 0);
    k_bn_partial<<<256, 256>>>(scv, psum, psq);
    k_bn_finalize<<<1, 256>>>(psum, psq, sc_g, sc_b, scsc, scsh);

    // 11) final fused: gate-combine + spike + shortcut BN + relu + NHWC->NCHW
    k_final<<<dim3(BB * 32, COUT / 32), tb32x8>>>(gate, retr, xf, scv, scsc, scsh, out);
}

// round 6
// speedup vs baseline: 2.0886x; 2.0886x over previous
#include <cuda_runtime.h>
#include <cstdint>
#include <cstddef>

// ---------------------------------------------------------------------------
// Problem constants
// ---------------------------------------------------------------------------
#define BB    32
#define CIN   128
#define COUT  256
#define HH    32
#define WW    32
#define HWP   1024              // H*W
#define MROWS 32768             // B*H*W
#define MEMN  64
#define EPSBN 1e-5f

// ---------------------------------------------------------------------------
// Scratch (single __device__ array; no allocations anywhere)
// ---------------------------------------------------------------------------
#define OFF_XN     0ull                      // 32768*128
#define OFF_T1     4194304ull                // 32768*256
#define OFF_T2     12582912ull
#define OFF_XF     20971520ull
#define OFF_RETR   29360128ull
#define OFF_GATE   37748736ull
#define OFF_SCV    46137344ull
#define OFF_L      54525952ull               // 32768*64
#define OFF_W1R    56623104ull               // 256*1152
#define OFF_W2R    56918016ull               // 256*2304
#define OFF_PSUM   57507840ull               // 256*256
#define OFF_PSQ    57573376ull
#define OFF_PAVG   57638912ull
#define OFF_PMAX   57704448ull
#define OFF_CATT   57769984ull               // 32*256
#define OFF_SPM    57778176ull               // 32768
#define OFF_SPX    57810944ull
#define OFF_SA     57843712ull
#define OFF_BN1SC  57876480ull               // 256 each
#define OFF_BN1SH  57876736ull
#define OFF_BN2SC  57876992ull
#define OFF_BN2SH  57877248ull
#define OFF_SCSC   57877504ull
#define OFF_SCSH   57877760ull
#define SCRATCH_TOTAL 57878016ull

__device__ float g_scratch[SCRATCH_TOTAL];

// ---------------------------------------------------------------------------
// tf32 helpers (plain sm_80+ PTX — compiles for sm_103 non-"a" target)
// ---------------------------------------------------------------------------
__device__ __forceinline__ uint32_t f2tf32(float x) {
    uint32_t r;
    asm("cvt.rna.tf32.f32 %0, %1;" : "=r"(r) : "f"(x));
    return r;
}
__device__ __forceinline__ void mma_tf32(float* d, const uint32_t* a, const uint32_t* b) {
    asm volatile(
        "mma.sync.aligned.m16n8k8.row.col.f32.tf32.tf32.f32 "
        "{%0,%1,%2,%3}, {%4,%5,%6,%7}, {%8,%9}, {%0,%1,%2,%3};"
        : "+f"(d[0]), "+f"(d[1]), "+f"(d[2]), "+f"(d[3])
        : "r"(a[0]), "r"(a[1]), "r"(a[2]), "r"(a[3]), "r"(b[0]), "r"(b[1]));
}

// ---------------------------------------------------------------------------
// tf32 tensor-core GEMM (mma.sync), fragment-native SMEM staging.
//   C[M,N] = alpha * A[M,K] * Wt[N,K]^T  (+bias)(relu|sigmoid)
// BM=128 (grid.x = M/128), BN template (grid.y = N/BN), BK=32, 256 thr.
// Modes:
//   c4shift==0 : A plain (K-concat: kg<Ksplit -> A[lda], else A2[lda2])
//   c4shift>0  : implicit im2col 3x3 pad1 over NHWC src A with C=1<<c4shift,
//                optional fused per-channel scale/shift + ReLU (BN).
// ---------------------------------------------------------------------------
#define F_BIAS 1
#define F_RELU 2
#define F_SIG  8

template<int BN>
__global__ void __launch_bounds__(256)
k_mma(const float* __restrict__ A, const float* __restrict__ A2, int Ksplit,
      int lda, int lda2, int c4shift,
      const float* __restrict__ scA, const float* __restrict__ shA,
      const float* __restrict__ Wt, int ldw,
      float* __restrict__ Cc, const float* __restrict__ bias,
      int N, int K, float alpha, int flags)
{
    constexpr int NB4  = BN / 32;            // B float4 loads per thread
    constexpr int NTW  = BN / 16;            // n-tiles (8 cols) per warp
    constexpr int ASZ  = 32 * 132;           // A stage floats (32 tiles * 132)
    constexpr int BSZ  = (BN / 8) * 4 * 66;  // B stage floats
    constexpr int STG  = ASZ + BSZ;

    extern __shared__ __align__(16) uint32_t dsm[];

    const int tid  = threadIdx.x;
    const int lane = tid & 31;
    const int wid  = tid >> 5;
    const int wm   = wid & 3;
    const int wn   = wid >> 2;
    const int bm   = blockIdx.x * 128;
    const int bn   = blockIdx.y * BN;

    float acc[2][NTW][4];
#pragma unroll
    for (int i = 0; i < 2; i++)
#pragma unroll
        for (int j = 0; j < NTW; j++)
#pragma unroll
            for (int q = 0; q < 4; q++) acc[i][j][q] = 0.f;

    uint32_t Areg[4][4];
    uint32_t Breg[NB4][4];

    auto loadA = [&](int k0) {
#pragma unroll
        for (int t = 0; t < 4; t++) {
            int idx = tid + t * 256;
            int r = idx >> 3, c4 = idx & 7;
            int kg = k0 + (c4 << 2);
            float4 v = make_float4(0.f, 0.f, 0.f, 0.f);
            if (c4shift) {
                int tap = kg >> c4shift;
                int ic  = kg & ((1 << c4shift) - 1);
                int t3  = tap / 3;
                int m   = bm + r;
                int yy  = ((m >> 5) & 31) + t3 - 1;
                int xx  = (m & 31) + (tap - t3 * 3) - 1;
                if ((unsigned)yy < 32u && (unsigned)xx < 32u) {
                    v = *(const float4*)(A +
                        (((size_t)((m >> 10) << 10) + (yy << 5) + xx) << c4shift) + ic);
                    if (scA) {
                        float4 sc = *(const float4*)(scA + ic);
                        float4 sh = *(const float4*)(shA + ic);
                        v.x = fmaxf(v.x * sc.x + sh.x, 0.f);
                        v.y = fmaxf(v.y * sc.y + sh.y, 0.f);
                        v.z = fmaxf(v.z * sc.z + sh.z, 0.f);
                        v.w = fmaxf(v.w * sc.w + sh.w, 0.f);
                    }
                }
            } else {
                const float* p;
                if (kg < Ksplit) p = A  + (size_t)(bm + r) * lda  + kg;
                else             p = A2 + (size_t)(bm + r) * lda2 + (kg - Ksplit);
                v = *(const float4*)p;
            }
            Areg[t][0] = f2tf32(v.x); Areg[t][1] = f2tf32(v.y);
            Areg[t][2] = f2tf32(v.z); Areg[t][3] = f2tf32(v.w);
        }
    };

    auto loadB = [&](int k0) {
#pragma unroll
        for (int t = 0; t < NB4; t++) {
            int idx = tid + t * 256;
            int r = idx >> 3, c4 = idx & 7;
            float4 v = *(const float4*)(Wt + (size_t)(bn + r) * ldw + k0 + (c4 << 2));
            Breg[t][0] = f2tf32(v.x); Breg[t][1] = f2tf32(v.y);
            Breg[t][2] = f2tf32(v.z); Breg[t][3] = f2tf32(v.w);
        }
    };

    auto stsA = [&](int st) {
        uint32_t* sA = dsm + st * STG;
#pragma unroll
        for (int t = 0; t < 4; t++) {
            int idx = tid + t * 256;
            int r = idx >> 3, c4 = idx & 7;
            int mt = r >> 4, rp = r & 15, kt = c4 >> 1;
            uint32_t* tp = sA + (mt * 4 + kt) * 132;
            int base = ((rp & 7) << 4) + (rp >> 3) + ((c4 & 1) << 1);
            tp[base + 0]  = Areg[t][0];
            tp[base + 4]  = Areg[t][1];
            tp[base + 8]  = Areg[t][2];
            tp[base + 12] = Areg[t][3];
        }
    };

    auto stsB = [&](int st) {
        uint32_t* sB = dsm + st * STG + ASZ;
#pragma unroll
        for (int t = 0; t < NB4; t++) {
            int idx = tid + t * 256;
            int r = idx >> 3, c4 = idx & 7;
            int nt = r >> 3, np = r & 7, kt = c4 >> 1;
            uint32_t* tp = sB + (nt * 4 + kt) * 66;
            int base = (np << 3) + (c4 & 1);
            tp[base + 0] = Breg[t][0];
            tp[base + 2] = Breg[t][1];
            tp[base + 4] = Breg[t][2];
            tp[base + 6] = Breg[t][3];
        }
    };

    auto compute = [&](int st) {
        const uint32_t* sA = dsm + st * STG;
        const uint32_t* sB = sA + ASZ;
#pragma unroll
        for (int kt = 0; kt < 4; kt++) {
            uint32_t af[2][4];
#pragma unroll
            for (int mt2 = 0; mt2 < 2; mt2++)
                *(uint4*)af[mt2] =
                    *(const uint4*)(sA + ((wm * 2 + mt2) * 4 + kt) * 132 + lane * 4);
            uint32_t bf[NTW][2];
#pragma unroll
            for (int nt2 = 0; nt2 < NTW; nt2++)
                *(uint2*)bf[nt2] =
                    *(const uint2*)(sB + ((wn * NTW + nt2) * 4 + kt) * 66 + lane * 2);
#pragma unroll
            for (int mt2 = 0; mt2 < 2; mt2++)
#pragma unroll
                for (int nt2 = 0; nt2 < NTW; nt2++)
                    mma_tf32(acc[mt2][nt2], af[mt2], bf[nt2]);
        }
    };

    const int nIter = K >> 5;
    loadA(0); loadB(0);
    stsA(0);  stsB(0);
    __syncthreads();
    for (int it = 0; it < nIter; ++it) {
        if (it + 1 < nIter) { loadA((it + 1) << 5); loadB((it + 1) << 5); }
        compute(it & 1);
        __syncthreads();
        if (it + 1 < nIter) {
            stsA((it + 1) & 1); stsB((it + 1) & 1);
            __syncthreads();
        }
    }

    // epilogue
    const int g = lane >> 2, t4 = lane & 3;
#pragma unroll
    for (int mt2 = 0; mt2 < 2; mt2++) {
#pragma unroll
        for (int nt2 = 0; nt2 < NTW; nt2++) {
            int row0 = bm + wm * 32 + mt2 * 16 + g;
            int col  = bn + wn * (NTW * 8) + nt2 * 8 + t4 * 2;
            float2 bv = (flags & F_BIAS) ? *(const float2*)(bias + col)
                                         : make_float2(0.f, 0.f);
#pragma unroll
            for (int h = 0; h < 2; h++) {
                float v0 = acc[mt2][nt2][h * 2 + 0] * alpha + bv.x;
                float v1 = acc[mt2][nt2][h * 2 + 1] * alpha + bv.y;
                if (flags & F_RELU) { v0 = fmaxf(v0, 0.f); v1 = fmaxf(v1, 0.f); }
                if (flags & F_SIG) {
                    v0 = 1.f / (1.f + expf(-v0));
                    v1 = 1.f / (1.f + expf(-v1));
                }
                *(float2*)(Cc + (size_t)(row0 + h * 8) * N + col) = make_float2(v0, v1);
            }
        }
    }
}

// ---------------------------------------------------------------------------
// NCHW -> NHWC transpose (x, C=128)
// ---------------------------------------------------------------------------
__global__ void k_nchw_to_nhwc(const float* __restrict__ src, float* __restrict__ dst, int C)
{
    __shared__ float tile[32][33];
    int b  = blockIdx.x >> 5;
    int p0 = (blockIdx.x & 31) << 5;
    int c0 = blockIdx.y << 5;
    for (int i = threadIdx.y; i < 32; i += 8)
        tile[i][threadIdx.x] = src[((size_t)b * C + c0 + i) * HWP + p0 + threadIdx.x];
    __syncthreads();
    for (int i = threadIdx.y; i < 32; i += 8)
        dst[((size_t)(b << 10) + p0 + i) * C + c0 + threadIdx.x] = tile[threadIdx.x][i];
}

// ---------------------------------------------------------------------------
// Weight reorder: w[n][ic][tap] -> wr[n][tap*Cin + ic]
// ---------------------------------------------------------------------------
__global__ void k_reorder_w(const float* __restrict__ w, float* __restrict__ wr, int Cin)
{
    int idx = blockIdx.x * 256 + threadIdx.x;
    int total = COUT * Cin * 9;
    if (idx >= total) return;
    int n   = idx / (Cin * 9);
    int rem = idx - n * (Cin * 9);
    int ic  = rem / 9;
    int tap = rem - ic * 9;
    wr[(size_t)n * Cin * 9 + tap * Cin + ic] = w[idx];
}

// ---------------------------------------------------------------------------
// Deterministic BN stats (two stage), 256 channels NHWC
// ---------------------------------------------------------------------------
__global__ void k_bn_partial(const float* __restrict__ t, float* __restrict__ psum,
                             float* __restrict__ psq)
{
    int c = threadIdx.x;
    int r0 = blockIdx.x * 128;
    float s = 0.f, s2 = 0.f;
    for (int r = 0; r < 128; r++) {
        float v = t[(size_t)(r0 + r) * 256 + c];
        s += v; s2 += v * v;
    }
    psum[blockIdx.x * 256 + c] = s;
    psq [blockIdx.x * 256 + c] = s2;
}

__global__ void k_bn_finalize(const float* __restrict__ psum, const float* __restrict__ psq,
                              const float* __restrict__ gamma, const float* __restrict__ beta,
                              float* __restrict__ scale, float* __restrict__ shift)
{
    int c = threadIdx.x;
    float s = 0.f, s2 = 0.f;
    for (int i = 0; i < 256; i++) { s += psum[i * 256 + c]; s2 += psq[i * 256 + c]; }
    float mean = s / 32768.f;
    float var  = s2 / 32768.f - mean * mean;
    float sc   = gamma[c] * rsqrtf(var + EPSBN);
    scale[c] = sc;
    shift[c] = beta[c] - mean * sc;
}

__global__ void k_bn_apply(float* __restrict__ t, const float* __restrict__ scale,
                           const float* __restrict__ shift)
{
    int idx = blockIdx.x * 256 + threadIdx.x;
    int c4 = idx & 63;
    float4 v  = ((float4*)t)[idx];
    float4 sc = ((const float4*)scale)[c4];
    float4 sh = ((const float4*)shift)[c4];
    v.x = v.x * sc.x + sh.x; v.y = v.y * sc.y + sh.y;
    v.z = v.z * sc.z + sh.z; v.w = v.w * sc.w + sh.w;
    ((float4*)t)[idx] = v;
}

// ---------------------------------------------------------------------------
// Channel attention
// ---------------------------------------------------------------------------
__global__ void k_ca_pool_partial(const float* __restrict__ t2, float* __restrict__ pavg,
                                  float* __restrict__ pmax)
{
    int b = blockIdx.x >> 3, ch = blockIdx.x & 7;
    int c = threadIdx.x;
    float s = 0.f, mx = -1e30f;
    for (int p = 0; p < 128; p++) {
        float v = t2[((size_t)(b << 10) + (ch << 7) + p) * 256 + c];
        s += v; mx = fmaxf(mx, v);
    }
    pavg[blockIdx.x * 256 + c] = s;
    pmax[blockIdx.x * 256 + c] = mx;
}

__global__ void k_ca_mlp(const float* __restrict__ pavg, const float* __restrict__ pmax,
                         const float* __restrict__ w1, const float* __restrict__ w2,
                         float* __restrict__ catt)
{
    __shared__ float av[256], mx[256], h[32];
    int b = blockIdx.x, c = threadIdx.x;
    float s = 0.f, m = -1e30f;
    for (int i = 0; i < 8; i++) {
        s += pavg[(b * 8 + i) * 256 + c];
        m = fmaxf(m, pmax[(b * 8 + i) * 256 + c]);
    }
    av[c] = s / 1024.f; mx[c] = m;
    __syncthreads();
    if (c < 32) {
        const float* src = (c < 16) ? av : mx;
        int j = c & 15;
        float acc = 0.f;
        for (int k = 0; k < 256; k++) acc += w1[j * 256 + k] * src[k];
        h[c] = fmaxf(acc, 0.f);
    }
    __syncthreads();
    float acc = 0.f;
#pragma unroll
    for (int j = 0; j < 16; j++) acc += w2[c * 16 + j] * (h[j] + h[16 + j]);
    catt[b * 256 + c] = 1.f / (1.f + expf(-acc));
}

// ---------------------------------------------------------------------------
// Spatial attention
// ---------------------------------------------------------------------------
__global__ void k_sp_pool(const float* __restrict__ t2, const float* __restrict__ catt,
                          float* __restrict__ spm, float* __restrict__ spx)
{
    int warp = threadIdx.x >> 5, lane = threadIdx.x & 31;
    int m = blockIdx.x * 8 + warp;
    int b = m >> 10;
    float s = 0.f, mx = -1e30f;
#pragma unroll
    for (int i = 0; i < 8; i++) {
        int c = i * 32 + lane;
        float v = t2[(size_t)m * 256 + c] * catt[b * 256 + c];
        s += v; mx = fmaxf(mx, v);
    }
    for (int o = 16; o; o >>= 1) {
        s += __shfl_xor_sync(0xffffffffu, s, o);
        mx = fmaxf(mx, __shfl_xor_sync(0xffffffffu, mx, o));
    }
    if (lane == 0) { spm[m] = s / 256.f; spx[m] = mx; }
}

__global__ void k_sa_conv(const float* __restrict__ spm, const float* __restrict__ spx,
                          const float* __restrict__ saw, const float* __restrict__ sab,
                          float* __restrict__ sa)
{
    __shared__ float sm[1024], sx[1024], w[98];
    int b = blockIdx.x, t = threadIdx.x;
    for (int i = t; i < 1024; i += 256) { sm[i] = spm[b * 1024 + i]; sx[i] = spx[b * 1024 + i]; }
    if (t < 98) w[t] = saw[t];
    __syncthreads();
    float bias = sab[0];
    for (int i = t; i < 1024; i += 256) {
        int y = i >> 5, x = i & 31;
        float acc = bias;
#pragma unroll
        for (int ky = 0; ky < 7; ky++) {
            int yy = y + ky - 3; if ((unsigned)yy >= 32u) continue;
#pragma unroll
            for (int kx = 0; kx < 7; kx++) {
                int xx = x + kx - 3; if ((unsigned)xx >= 32u) continue;
                acc += w[ky * 7 + kx] * sm[yy * 32 + xx] + w[49 + ky * 7 + kx] * sx[yy * 32 + xx];
            }
        }
        sa[b * 1024 + i] = 1.f / (1.f + expf(-acc));
    }
}

__global__ void k_apply_att(const float* __restrict__ t2, const float* __restrict__ catt,
                            const float* __restrict__ sa, float* __restrict__ xf)
{
    int idx = blockIdx.x * 256 + threadIdx.x;
    int m = idx >> 6, c4 = idx & 63;
    int b = m >> 10;
    float s = sa[m];
    float4 v  = ((const float4*)t2)[idx];
    float4 ca = ((const float4*)(catt + b * 256))[c4];
    v.x *= ca.x * s; v.y *= ca.y * s; v.z *= ca.z * s; v.w *= ca.w * s;
    ((float4*)xf)[idx] = v;
}

// ---------------------------------------------------------------------------
// Fused softmax over 64 logits + retrieved = attn @ mem. Warp per row.
// ---------------------------------------------------------------------------
__global__ void k_softmax_retrieve(const float* __restrict__ L, const float* __restrict__ mem,
                                   float* __restrict__ retr)
{
    extern __shared__ float ms[];
    for (int i = threadIdx.x; i < 16384; i += 256) ms[i] = mem[i];
    __syncthreads();
    int warp = threadIdx.x >> 5, lane = threadIdx.x & 31;
    int m = blockIdx.x * 8 + warp;
    float l0 = L[(size_t)m * 64 + lane];
    float l1 = L[(size_t)m * 64 + 32 + lane];
    float mx = fmaxf(l0, l1);
    for (int o = 16; o; o >>= 1) mx = fmaxf(mx, __shfl_xor_sync(0xffffffffu, mx, o));
    float e0 = expf(l0 - mx), e1 = expf(l1 - mx);
    float s = e0 + e1;
    for (int o = 16; o; o >>= 1) s += __shfl_xor_sync(0xffffffffu, s, o);
    float inv = 1.f / s;
    e0 *= inv; e1 *= inv;
    float acc[8] = {};
    for (int j = 0; j < 32; j++) {
        float a0 = __shfl_sync(0xffffffffu, e0, j);
        float a1 = __shfl_sync(0xffffffffu, e1, j);
#pragma unroll
        for (int f = 0; f < 8; f++)
            acc[f] += a0 * ms[j * 256 + f * 32 + lane] + a1 * ms[(j + 32) * 256 + f * 32 + lane];
    }
#pragma unroll
    for (int f = 0; f < 8; f++) retr[(size_t)m * 256 + f * 32 + lane] = acc[f];
}

// ---------------------------------------------------------------------------
// Final fused epilogue with NHWC->NCHW transpose
// ---------------------------------------------------------------------------
__global__ void k_final(const float* __restrict__ g, const float* __restrict__ retr,
                        const float* __restrict__ xf, const float* __restrict__ scv,
                        const float* __restrict__ scScale, const float* __restrict__ scShift,
                        float* __restrict__ out)
{
    __shared__ float tile[32][33];
    int b = blockIdx.x >> 5, p0 = (blockIdx.x & 31) << 5, c0 = blockIdx.y << 5;
    int tx = threadIdx.x, ty = threadIdx.y;
    for (int i = ty; i < 32; i += 8) {
        int m = (b << 10) + p0 + i;
        int c = c0 + tx;
        size_t id = (size_t)m * 256 + c;
        float gg = g[id], rr = retr[id], xx = xf[id];
        float mo = gg * rr + (1.f - gg) * xx;
        float spike = (0.1f * mo >= 1.f) ? 1.f : 0.f;
        float idn = scv[id] * scScale[c] + scShift[c];
        tile[tx][i] = fmaxf(spike + idn, 0.f);
    }
    __syncthreads();
    for (int i = ty; i < 32; i += 8)
        out[((size_t)b * 256 + c0 + i) * HWP + p0 + tx] = tile[i][tx];
}

// ---------------------------------------------------------------------------
// Launch
// ---------------------------------------------------------------------------
extern "C" void kernel_launch(void* const* d_in, const int* in_sizes, int n_in,
                              void* d_out, int out_size)
{
    const float* x        = (const float*)d_in[0];
    const float* conv1_w  = (const float*)d_in[1];
    const float* conv1_b  = (const float*)d_in[2];
    const float* bn1_g    = (const float*)d_in[3];
    const float* bn1_b    = (const float*)d_in[4];
    const float* conv2_w  = (const float*)d_in[5];
    const float* conv2_b  = (const float*)d_in[6];
    const float* bn2_g    = (const float*)d_in[7];
    const float* bn2_b    = (const float*)d_in[8];
    const float* ca_w1    = (const float*)d_in[9];
    const float* ca_w2    = (const float*)d_in[10];
    const float* sa_w     = (const float*)d_in[11];
    const float* sa_b     = (const float*)d_in[12];
    const float* memv     = (const float*)d_in[13];
    const float* mem_keys = (const float*)d_in[14];
    const float* ctrl_w1  = (const float*)d_in[15];
    const float* ctrl_b1  = (const float*)d_in[16];
    const float* ctrl_w2  = (const float*)d_in[17];
    const float* ctrl_b2  = (const float*)d_in[18];
    const float* gate_w   = (const float*)d_in[19];
    const float* gate_b   = (const float*)d_in[20];
    const float* sc_w     = (const float*)d_in[21];
    const float* sc_g     = (const float*)d_in[22];
    const float* sc_b     = (const float*)d_in[23];
    float* out = (float*)d_out;

    void* basep = nullptr;
    cudaGetSymbolAddress(&basep, g_scratch);
    float* S = (float*)basep;

    float* xn    = S + OFF_XN;
    float* t1    = S + OFF_T1;
    float* t2    = S + OFF_T2;
    float* xf    = S + OFF_XF;
    float* retr  = S + OFF_RETR;
    float* gate  = S + OFF_GATE;
    float* scv   = S + OFF_SCV;
    float* Lbuf  = S + OFF_L;
    float* w1r   = S + OFF_W1R;
    float* w2r   = S + OFF_W2R;
    float* psum  = S + OFF_PSUM;
    float* psq   = S + OFF_PSQ;
    float* pavg  = S + OFF_PAVG;
    float* pmax  = S + OFF_PMAX;
    float* catt  = S + OFF_CATT;
    float* spm   = S + OFF_SPM;
    float* spx   = S + OFF_SPX;
    float* sa    = S + OFF_SA;
    float* bn1sc = S + OFF_BN1SC;  float* bn1sh = S + OFF_BN1SH;
    float* bn2sc = S + OFF_BN2SC;  float* bn2sh = S + OFF_BN2SH;
    float* scsc  = S + OFF_SCSC;   float* scsh  = S + OFF_SCSH;

    // dynamic smem: BN=128: 2*(32*132 + 64*66)*4 = 67584 B ; BN=64: 50688 B
    const int dyn128 = 2 * (32 * 132 + 64 * 66) * 4;
    const int dyn64  = 2 * (32 * 132 + 32 * 66) * 4;
    cudaFuncSetAttribute(k_mma<128>, cudaFuncAttributeMaxDynamicSharedMemorySize, dyn128);
    cudaFuncSetAttribute(k_mma<64>,  cudaFuncAttributeMaxDynamicSharedMemorySize, dyn64);
    cudaFuncSetAttribute(k_softmax_retrieve, cudaFuncAttributeMaxDynamicSharedMemorySize, 65536);

    dim3 tb32x8(32, 8);
    dim3 g2(MROWS / 128, 2);   // N=256 tiles
    dim3 g1(MROWS / 128, 1);   // N=64 tiles

    // 1) x -> NHWC
    k_nchw_to_nhwc<<<dim3(BB * 32, CIN / 32), tb32x8>>>(x, xn, CIN);

    // 2) weight reorders (tap-major K)
    k_reorder_w<<<(COUT * CIN * 9 + 255) / 256, 256>>>(conv1_w, w1r, CIN);
    k_reorder_w<<<(COUT * COUT * 9 + 255) / 256, 256>>>(conv2_w, w2r, COUT);

    // 3) conv1: implicit im2col GEMM (+bias) -> t1
    k_mma<128><<<g2, 256, dyn128>>>(xn, nullptr, 1 << 30, 0, 0, 7, nullptr, nullptr,
                                    w1r, 9 * CIN, t1, conv1_b,
                                    COUT, 9 * CIN, 1.f, F_BIAS);

    // 4) BN1 stats (application fused into conv2 A-loader)
    k_bn_partial<<<256, 256>>>(t1, psum, psq);
    k_bn_finalize<<<1, 256>>>(psum, psq, bn1_g, bn1_b, bn1sc, bn1sh);

    // 5) conv2: implicit im2col GEMM with fused BN1+ReLU (+bias) -> t2
    k_mma<128><<<g2, 256, dyn128>>>(t1, nullptr, 1 << 30, 0, 0, 8, bn1sc, bn1sh,
                                    w2r, 9 * COUT, t2, conv2_b,
                                    COUT, 9 * COUT, 1.f, F_BIAS);

    // 6) BN2 stats + apply in place
    k_bn_partial<<<256, 256>>>(t2, psum, psq);
    k_bn_finalize<<<1, 256>>>(psum, psq, bn2_g, bn2_b, bn2sc, bn2sh);
    k_bn_apply<<<MROWS * 64 / 256, 256>>>(t2, bn2sc, bn2sh);

    // 7) channel attention
    k_ca_pool_partial<<<BB * 8, 256>>>(t2, pavg, pmax);
    k_ca_mlp<<<BB, 256>>>(pavg, pmax, ca_w1, ca_w2, catt);

    // 8) spatial attention
    k_sp_pool<<<MROWS / 8, 256>>>(t2, catt, spm, spx);
    k_sa_conv<<<BB, 256>>>(spm, spx, sa_w, sa_b, sa);
    k_apply_att<<<MROWS * 64 / 256, 256>>>(t2, catt, sa, xf);

    // 9) memory module
    k_mma<128><<<g2, 256, dyn128>>>(xf, nullptr, 1 << 30, COUT, 0, 0, nullptr, nullptr,
                                    ctrl_w1, COUT, t1, ctrl_b1,
                                    COUT, COUT, 1.f, F_BIAS | F_RELU);
    k_mma<128><<<g2, 256, dyn128>>>(t1, nullptr, 1 << 30, COUT, 0, 0, nullptr, nullptr,
                                    ctrl_w2, COUT, t2, ctrl_b2,
                                    COUT, COUT, 1.f, F_BIAS);
    k_mma<64><<<g1, 256, dyn64>>>(t2, nullptr, 1 << 30, COUT, 0, 0, nullptr, nullptr,
                                  mem_keys, COUT, Lbuf, nullptr,
                                  MEMN, COUT, 1.f / 16.f, 0);
    k_softmax_retrieve<<<MROWS / 8, 256, 65536>>>(Lbuf, memv, retr);
    // gate = sigmoid([xf | retr] @ gate_w^T + gb) — K-concat
    k_mma<128><<<g2, 256, dyn128>>>(xf, retr, COUT, COUT, COUT, 0, nullptr, nullptr,
                                    gate_w, 2 * COUT, gate, gate_b,
                                    COUT, 2 * COUT, 1.f, F_BIAS | F_SIG);

    // 10) shortcut 1x1 conv + BN stats
    k_mma<128><<<g2, 256, dyn128>>>(xn, nullptr, 1 << 30, CIN, 0, 0, nullptr, nullptr,
                                    sc_w, CIN, scv, nullptr,
                                    COUT, CIN, 1.f, 0);
    k_bn_partial<<<256, 256>>>(scv, psum, psq);
    k_bn_finalize<<<1, 256>>>(psum, psq, sc_g, sc_b, scsc, scsh);

    // 11) final fused epilogue
    k_final<<<dim3(BB * 32, COUT / 32), tb32x8>>>(gate, retr, xf, scv, scsc, scsh, out);
}

// round 8
// speedup vs baseline: 2.3882x; 1.1434x over previous
#include <cuda_runtime.h>
#include <cstdint>
#include <cstddef>

// ---------------------------------------------------------------------------
// Problem constants
// ---------------------------------------------------------------------------
#define BB    32
#define CIN   128
#define COUT  256
#define HH    32
#define WW    32
#define HWP   1024              // H*W
#define MROWS 32768             // B*H*W
#define MEMN  64
#define EPSBN 1e-5f

// ---------------------------------------------------------------------------
// Scratch (single __device__ array; no allocations anywhere)
// ---------------------------------------------------------------------------
#define OFF_XN     0ull                      // 32768*128
#define OFF_T1     4194304ull                // 32768*256
#define OFF_T2     12582912ull
#define OFF_XF     20971520ull
#define OFF_RETR   29360128ull
#define OFF_GATE   37748736ull
#define OFF_SCV    46137344ull
#define OFF_L      54525952ull               // 32768*64
#define OFF_W1R    56623104ull               // 256*1152
#define OFF_W2R    56918016ull               // 256*2304
#define OFF_W3R    57507840ull               // 256*256  (ctrl_w1 rounded)
#define OFF_WGR    57573376ull               // 256*512  (gate_w rounded)
#define OFF_WSCR   57704448ull               // 256*128  (sc_w rounded)
#define OFF_KW     57737216ull               // 64*256   (keys @ ctrl_w2, rounded)
#define OFF_KB     57753600ull               // 64 (padded 256)
#define OFF_PSUM   57753856ull               // 256*256
#define OFF_PSQ    57819392ull
#define OFF_PAVG   57884928ull
#define OFF_PMAX   57950464ull
#define OFF_CATT   58016000ull               // 32*256
#define OFF_SPM    58024192ull               // 32768
#define OFF_SPX    58056960ull
#define OFF_SA     58089728ull
#define OFF_BN1SC  58122496ull               // 256 each
#define OFF_BN1SH  58122752ull
#define OFF_BN2SC  58123008ull
#define OFF_BN2SH  58123264ull
#define OFF_SCSC   58123520ull
#define OFF_SCSH   58123776ull
#define SCRATCH_TOTAL 58124032ull

__device__ float g_scratch[SCRATCH_TOTAL];

// ---------------------------------------------------------------------------
// tf32 helpers (plain sm_80+ PTX — compiles for sm_103 non-"a" target)
// ---------------------------------------------------------------------------
__device__ __forceinline__ uint32_t f2tf32(float x) {
    uint32_t r;
    asm("cvt.rna.tf32.f32 %0, %1;" : "=r"(r) : "f"(x));
    return r;
}
__device__ __forceinline__ float tf32f(float x) {
    return __uint_as_float(f2tf32(x));
}
__device__ __forceinline__ void mma_tf32(float* d, const uint32_t* a, const uint32_t* b) {
    asm volatile(
        "mma.sync.aligned.m16n8k8.row.col.f32.tf32.tf32.f32 "
        "{%0,%1,%2,%3}, {%4,%5,%6,%7}, {%8,%9}, {%0,%1,%2,%3};"
        : "+f"(d[0]), "+f"(d[1]), "+f"(d[2]), "+f"(d[3])
        : "r"(a[0]), "r"(a[1]), "r"(a[2]), "r"(a[3]), "r"(b[0]), "r"(b[1]));
}

// ---------------------------------------------------------------------------
// tf32 tensor-core GEMM (mma.sync), fragment-native SMEM staging.
//   C[M,N] = alpha * A[M,K] * Wt[N,K]^T  (+bias)(relu|sigmoid)(tf32-round)
// BM=128 (grid.x = M/128), BN template (grid.y = N/BN), BK=32, 256 thr.
// A/B operands must be tf32-pre-rounded UNLESS scA!=null (conv2 BN path,
// which converts explicitly after applying scale/shift).
// ---------------------------------------------------------------------------
#define F_BIAS 1
#define F_RELU 2
#define F_SIG  8
#define F_TF32 16

template<int BN>
__global__ void __launch_bounds__(256)
k_mma(const float* __restrict__ A, const float* __restrict__ A2, int Ksplit,
      int lda, int lda2, int c4shift,
      const float* __restrict__ scA, const float* __restrict__ shA,
      const float* __restrict__ Wt, int ldw,
      float* __restrict__ Cc, const float* __restrict__ bias,
      int N, int K, float alpha, int flags)
{
    constexpr int NB4  = BN / 32;            // B float4 loads per thread
    constexpr int NTW  = BN / 16;            // n-tiles (8 cols) per warp
    constexpr int ASZ  = 32 * 132;           // A stage floats
    constexpr int BSZ  = (BN / 8) * 4 * 66;  // B stage floats
    constexpr int STG  = ASZ + BSZ;

    extern __shared__ __align__(16) uint32_t dsm[];

    const int tid  = threadIdx.x;
    const int lane = tid & 31;
    const int wid  = tid >> 5;
    const int wm   = wid & 3;
    const int wn   = wid >> 2;
    const int bm   = blockIdx.x * 128;
    const int bn   = blockIdx.y * BN;

    float acc[2][NTW][4];
#pragma unroll
    for (int i = 0; i < 2; i++)
#pragma unroll
        for (int j = 0; j < NTW; j++)
#pragma unroll
            for (int q = 0; q < 4; q++) acc[i][j][q] = 0.f;

    uint32_t Areg[4][4];
    uint32_t Breg[NB4][4];

    const bool doCvt = (scA != nullptr);

    auto loadA = [&](int k0) {
#pragma unroll
        for (int t = 0; t < 4; t++) {
            int idx = tid + t * 256;
            int r = idx >> 3, c4 = idx & 7;
            int kg = k0 + (c4 << 2);
            float4 v = make_float4(0.f, 0.f, 0.f, 0.f);
            if (c4shift) {
                int tap = kg >> c4shift;
                int ic  = kg & ((1 << c4shift) - 1);
                int t3  = tap / 3;
                int m   = bm + r;
                int yy  = ((m >> 5) & 31) + t3 - 1;
                int xx  = (m & 31) + (tap - t3 * 3) - 1;
                if ((unsigned)yy < 32u && (unsigned)xx < 32u) {
                    v = *(const float4*)(A +
                        (((size_t)((m >> 10) << 10) + (yy << 5) + xx) << c4shift) + ic);
                    if (doCvt) {
                        float4 sc = *(const float4*)(scA + ic);
                        float4 sh = *(const float4*)(shA + ic);
                        v.x = fmaxf(v.x * sc.x + sh.x, 0.f);
                        v.y = fmaxf(v.y * sc.y + sh.y, 0.f);
                        v.z = fmaxf(v.z * sc.z + sh.z, 0.f);
                        v.w = fmaxf(v.w * sc.w + sh.w, 0.f);
                    }
                }
            } else {
                const float* p;
                if (kg < Ksplit) p = A  + (size_t)(bm + r) * lda  + kg;
                else             p = A2 + (size_t)(bm + r) * lda2 + (kg - Ksplit);
                v = *(const float4*)p;
            }
            if (doCvt) {
                Areg[t][0] = f2tf32(v.x); Areg[t][1] = f2tf32(v.y);
                Areg[t][2] = f2tf32(v.z); Areg[t][3] = f2tf32(v.w);
            } else {
                Areg[t][0] = __float_as_uint(v.x); Areg[t][1] = __float_as_uint(v.y);
                Areg[t][2] = __float_as_uint(v.z); Areg[t][3] = __float_as_uint(v.w);
            }
        }
    };

    auto loadB = [&](int k0) {
#pragma unroll
        for (int t = 0; t < NB4; t++) {
            int idx = tid + t * 256;
            int r = idx >> 3, c4 = idx & 7;
            float4 v = *(const float4*)(Wt + (size_t)(bn + r) * ldw + k0 + (c4 << 2));
            Breg[t][0] = __float_as_uint(v.x); Breg[t][1] = __float_as_uint(v.y);
            Breg[t][2] = __float_as_uint(v.z); Breg[t][3] = __float_as_uint(v.w);
        }
    };

    auto stsA = [&](int st) {
        uint32_t* sA = dsm + st * STG;
#pragma unroll
        for (int t = 0; t < 4; t++) {
            int idx = tid + t * 256;
            int r = idx >> 3, c4 = idx & 7;
            int mt = r >> 4, rp = r & 15, kt = c4 >> 1;
            uint32_t* tp = sA + (mt * 4 + kt) * 132;
            int base = ((rp & 7) << 4) + (rp >> 3) + ((c4 & 1) << 1);
            tp[base + 0]  = Areg[t][0];
            tp[base + 4]  = Areg[t][1];
            tp[base + 8]  = Areg[t][2];
            tp[base + 12] = Areg[t][3];
        }
    };

    auto stsB = [&](int st) {
        uint32_t* sB = dsm + st * STG + ASZ;
#pragma unroll
        for (int t = 0; t < NB4; t++) {
            int idx = tid + t * 256;
            int r = idx >> 3, c4 = idx & 7;
            int nt = r >> 3, np = r & 7, kt = c4 >> 1;
            uint32_t* tp = sB + (nt * 4 + kt) * 66;
            int base = (np << 3) + (c4 & 1);
            tp[base + 0] = Breg[t][0];
            tp[base + 2] = Breg[t][1];
            tp[base + 4] = Breg[t][2];
            tp[base + 6] = Breg[t][3];
        }
    };

    auto compute = [&](int st) {
        const uint32_t* sA = dsm + st * STG;
        const uint32_t* sB = sA + ASZ;
#pragma unroll
        for (int kt = 0; kt < 4; kt++) {
            uint32_t af[2][4];
#pragma unroll
            for (int mt2 = 0; mt2 < 2; mt2++)
                *(uint4*)af[mt2] =
                    *(const uint4*)(sA + ((wm * 2 + mt2) * 4 + kt) * 132 + lane * 4);
            uint32_t bf[NTW][2];
#pragma unroll
            for (int nt2 = 0; nt2 < NTW; nt2++)
                *(uint2*)bf[nt2] =
                    *(const uint2*)(sB + ((wn * NTW + nt2) * 4 + kt) * 66 + lane * 2);
#pragma unroll
            for (int mt2 = 0; mt2 < 2; mt2++)
#pragma unroll
                for (int nt2 = 0; nt2 < NTW; nt2++)
                    mma_tf32(acc[mt2][nt2], af[mt2], bf[nt2]);
        }
    };

    const int nIter = K >> 5;
    loadA(0); loadB(0);
    stsA(0);  stsB(0);
    if (nIter > 1) { loadA(32); loadB(32); }
    __syncthreads();
    for (int it = 0; it < nIter; ++it) {
        if (it + 1 < nIter) { stsA((it + 1) & 1); stsB((it + 1) & 1); }
        if (it + 2 < nIter) { loadA((it + 2) << 5); loadB((it + 2) << 5); }
        compute(it & 1);
        __syncthreads();
    }

    // epilogue
    const int g = lane >> 2, t4 = lane & 3;
#pragma unroll
    for (int mt2 = 0; mt2 < 2; mt2++) {
#pragma unroll
        for (int nt2 = 0; nt2 < NTW; nt2++) {
            int row0 = bm + wm * 32 + mt2 * 16 + g;
            int col  = bn + wn * (NTW * 8) + nt2 * 8 + t4 * 2;
            float2 bv = (flags & F_BIAS) ? *(const float2*)(bias + col)
                                         : make_float2(0.f, 0.f);
#pragma unroll
            for (int h = 0; h < 2; h++) {
                float v0 = acc[mt2][nt2][h * 2 + 0] * alpha + bv.x;
                float v1 = acc[mt2][nt2][h * 2 + 1] * alpha + bv.y;
                if (flags & F_RELU) { v0 = fmaxf(v0, 0.f); v1 = fmaxf(v1, 0.f); }
                if (flags & F_SIG) {
                    v0 = 1.f / (1.f + expf(-v0));
                    v1 = 1.f / (1.f + expf(-v1));
                }
                if (flags & F_TF32) { v0 = tf32f(v0); v1 = tf32f(v1); }
                *(float2*)(Cc + (size_t)(row0 + h * 8) * N + col) = make_float2(v0, v1);
            }
        }
    }
}

// ---------------------------------------------------------------------------
// NCHW -> NHWC transpose (x, C=128), output tf32-rounded
// ---------------------------------------------------------------------------
__global__ void k_nchw_to_nhwc(const float* __restrict__ src, float* __restrict__ dst, int C)
{
    __shared__ float tile[32][33];
    int b  = blockIdx.x >> 5;
    int p0 = (blockIdx.x & 31) << 5;
    int c0 = blockIdx.y << 5;
    for (int i = threadIdx.y; i < 32; i += 8)
        tile[i][threadIdx.x] = src[((size_t)b * C + c0 + i) * HWP + p0 + threadIdx.x];
    __syncthreads();
    for (int i = threadIdx.y; i < 32; i += 8)
        dst[((size_t)(b << 10) + p0 + i) * C + c0 + threadIdx.x] = tf32f(tile[threadIdx.x][i]);
}

// ---------------------------------------------------------------------------
// Weight reorder: w[n][ic][tap] -> wr[n][tap*Cin + ic], tf32-rounded
// ---------------------------------------------------------------------------
__global__ void k_reorder_w(const float* __restrict__ w, float* __restrict__ wr, int Cin)
{
    int idx = blockIdx.x * 256 + threadIdx.x;
    int total = COUT * Cin * 9;
    if (idx >= total) return;
    int n   = idx / (Cin * 9);
    int rem = idx - n * (Cin * 9);
    int ic  = rem / 9;
    int tap = rem - ic * 9;
    wr[(size_t)n * Cin * 9 + tap * Cin + ic] = tf32f(w[idx]);
}

// Generic elementwise tf32 rounding
__global__ void k_round(const float* __restrict__ in, float* __restrict__ out, int n)
{
    int i = blockIdx.x * 256 + threadIdx.x;
    if (i < n) out[i] = tf32f(in[i]);
}

// ---------------------------------------------------------------------------
// Fold mem_keys into ctrl_w2: KW[j,k] = sum_c keys[j,c]*W2[c,k] (tf32),
// kb[j] = (keys[j,:] . b2) / 16
// ---------------------------------------------------------------------------
__global__ void k_keyfold(const float* __restrict__ keys, const float* __restrict__ W2,
                          const float* __restrict__ b2,
                          float* __restrict__ KW, float* __restrict__ kb)
{
    __shared__ float krow[256];
    __shared__ float red[256];
    int j = blockIdx.x, t = threadIdx.x;
    krow[t] = keys[j * 256 + t];
    __syncthreads();
    float acc = 0.f;
    for (int c = 0; c < 256; c++) acc += krow[c] * W2[c * 256 + t];
    KW[j * 256 + t] = tf32f(acc);
    red[t] = krow[t] * b2[t];
    __syncthreads();
    for (int o = 128; o; o >>= 1) { if (t < o) red[t] += red[t + o]; __syncthreads(); }
    if (t == 0) kb[j] = red[0] * (1.f / 16.f);
}

// ---------------------------------------------------------------------------
// Deterministic BN stats (two stage), 256 channels NHWC
// ---------------------------------------------------------------------------
__global__ void k_bn_partial(const float* __restrict__ t, float* __restrict__ psum,
                             float* __restrict__ psq)
{
    int c = threadIdx.x;
    int r0 = blockIdx.x * 128;
    float s = 0.f, s2 = 0.f;
    for (int r = 0; r < 128; r++) {
        float v = t[(size_t)(r0 + r) * 256 + c];
        s += v; s2 += v * v;
    }
    psum[blockIdx.x * 256 + c] = s;
    psq [blockIdx.x * 256 + c] = s2;
}

__global__ void k_bn_finalize(const float* __restrict__ psum, const float* __restrict__ psq,
                              const float* __restrict__ gamma, const float* __restrict__ beta,
                              float* __restrict__ scale, float* __restrict__ shift)
{
    int c = threadIdx.x;
    float s = 0.f, s2 = 0.f;
    for (int i = 0; i < 256; i++) { s += psum[i * 256 + c]; s2 += psq[i * 256 + c]; }
    float mean = s / 32768.f;
    float var  = s2 / 32768.f - mean * mean;
    float sc   = gamma[c] * rsqrtf(var + EPSBN);
    scale[c] = sc;
    shift[c] = beta[c] - mean * sc;
}

// ---------------------------------------------------------------------------
// Channel attention (BN2 fused: v = t2*sc + sh)
// ---------------------------------------------------------------------------
__global__ void k_ca_pool_partial(const float* __restrict__ t2,
                                  const float* __restrict__ bsc, const float* __restrict__ bsh,
                                  float* __restrict__ pavg, float* __restrict__ pmax)
{
    int b = blockIdx.x >> 3, ch = blockIdx.x & 7;
    int c = threadIdx.x;
    float scv = bsc[c], shv = bsh[c];
    float s = 0.f, mx = -1e30f;
    for (int p = 0; p < 128; p++) {
        float v = t2[((size_t)(b << 10) + (ch << 7) + p) * 256 + c] * scv + shv;
        s += v; mx = fmaxf(mx, v);
    }
    pavg[blockIdx.x * 256 + c] = s;
    pmax[blockIdx.x * 256 + c] = mx;
}

__global__ void k_ca_mlp(const float* __restrict__ pavg, const float* __restrict__ pmax,
                         const float* __restrict__ w1, const float* __restrict__ w2,
                         float* __restrict__ catt)
{
    __shared__ float av[256], mx[256], h[32];
    int b = blockIdx.x, c = threadIdx.x;
    float s = 0.f, m = -1e30f;
    for (int i = 0; i < 8; i++) {
        s += pavg[(b * 8 + i) * 256 + c];
        m = fmaxf(m, pmax[(b * 8 + i) * 256 + c]);
    }
    av[c] = s / 1024.f; mx[c] = m;
    __syncthreads();
    if (c < 32) {
        const float* src = (c < 16) ? av : mx;
        int j = c & 15;
        float acc = 0.f;
        for (int k = 0; k < 256; k++) acc += w1[j * 256 + k] * src[k];
        h[c] = fmaxf(acc, 0.f);
    }
    __syncthreads();
    float acc = 0.f;
#pragma unroll
    for (int j = 0; j < 16; j++) acc += w2[c * 16 + j] * (h[j] + h[16 + j]);
    catt[b * 256 + c] = 1.f / (1.f + expf(-acc));
}

// ---------------------------------------------------------------------------
// Spatial attention (BN2 fused)
// ---------------------------------------------------------------------------
__global__ void k_sp_pool(const float* __restrict__ t2,
                          const float* __restrict__ bsc, const float* __restrict__ bsh,
                          const float* __restrict__ catt,
                          float* __restrict__ spm, float* __restrict__ spx)
{
    int warp = threadIdx.x >> 5, lane = threadIdx.x & 31;
    int m = blockIdx.x * 8 + warp;
    int b = m >> 10;
    float s = 0.f, mx = -1e30f;
#pragma unroll
    for (int i = 0; i < 8; i++) {
        int c = i * 32 + lane;
        float v = (t2[(size_t)m * 256 + c] * bsc[c] + bsh[c]) * catt[b * 256 + c];
        s += v; mx = fmaxf(mx, v);
    }
    for (int o = 16; o; o >>= 1) {
        s += __shfl_xor_sync(0xffffffffu, s, o);
        mx = fmaxf(mx, __shfl_xor_sync(0xffffffffu, mx, o));
    }
    if (lane == 0) { spm[m] = s / 256.f; spx[m] = mx; }
}

__global__ void k_sa_conv(const float* __restrict__ spm, const float* __restrict__ spx,
                          const float* __restrict__ saw, const float* __restrict__ sab,
                          float* __restrict__ sa)
{
    __shared__ float sm[1024], sx[1024], w[98];
    int b = blockIdx.x, t = threadIdx.x;
    for (int i = t; i < 1024; i += 256) { sm[i] = spm[b * 1024 + i]; sx[i] = spx[b * 1024 + i]; }
    if (t < 98) w[t] = saw[t];
    __syncthreads();
    float bias = sab[0];
    for (int i = t; i < 1024; i += 256) {
        int y = i >> 5, x = i & 31;
        float acc = bias;
#pragma unroll
        for (int ky = 0; ky < 7; ky++) {
            int yy = y + ky - 3; if ((unsigned)yy >= 32u) continue;
#pragma unroll
            for (int kx = 0; kx < 7; kx++) {
                int xx = x + kx - 3; if ((unsigned)xx >= 32u) continue;
                acc += w[ky * 7 + kx] * sm[yy * 32 + xx] + w[49 + ky * 7 + kx] * sx[yy * 32 + xx];
            }
        }
        sa[b * 1024 + i] = 1.f / (1.f + expf(-acc));
    }
}

// xf = tf32( (t2*bsc+bsh) * catt * sa )
__global__ void k_apply_att(const float* __restrict__ t2,
                            const float* __restrict__ bsc, const float* __restrict__ bsh,
                            const float* __restrict__ catt,
                            const float* __restrict__ sa, float* __restrict__ xf)
{
    int idx = blockIdx.x * 256 + threadIdx.x;
    int m = idx >> 6, c4 = idx & 63;
    int b = m >> 10;
    float s = sa[m];
    float4 v  = ((const float4*)t2)[idx];
    float4 sc = ((const float4*)bsc)[c4];
    float4 sh = ((const float4*)bsh)[c4];
    float4 ca = ((const float4*)(catt + b * 256))[c4];
    v.x = tf32f((v.x * sc.x + sh.x) * ca.x * s);
    v.y = tf32f((v.y * sc.y + sh.y) * ca.y * s);
    v.z = tf32f((v.z * sc.z + sh.z) * ca.z * s);
    v.w = tf32f((v.w * sc.w + sh.w) * ca.w * s);
    ((float4*)xf)[idx] = v;
}

// ---------------------------------------------------------------------------
// Fused softmax over 64 logits + retrieved = attn @ mem. Warp per row.
// retr output tf32-rounded.
// ---------------------------------------------------------------------------
__global__ void k_softmax_retrieve(const float* __restrict__ L, const float* __restrict__ mem,
                                   float* __restrict__ retr)
{
    extern __shared__ float ms[];
    for (int i = threadIdx.x; i < 16384; i += 256) ms[i] = mem[i];
    __syncthreads();
    int warp = threadIdx.x >> 5, lane = threadIdx.x & 31;
    int m = blockIdx.x * 8 + warp;
    float l0 = L[(size_t)m * 64 + lane];
    float l1 = L[(size_t)m * 64 + 32 + lane];
    float mx = fmaxf(l0, l1);
    for (int o = 16; o; o >>= 1) mx = fmaxf(mx, __shfl_xor_sync(0xffffffffu, mx, o));
    float e0 = expf(l0 - mx), e1 = expf(l1 - mx);
    float s = e0 + e1;
    for (int o = 16; o; o >>= 1) s += __shfl_xor_sync(0xffffffffu, s, o);
    float inv = 1.f / s;
    e0 *= inv; e1 *= inv;
    float acc[8] = {};
    for (int j = 0; j < 32; j++) {
        float a0 = __shfl_sync(0xffffffffu, e0, j);
        float a1 = __shfl_sync(0xffffffffu, e1, j);
#pragma unroll
        for (int f = 0; f < 8; f++)
            acc[f] += a0 * ms[j * 256 + f * 32 + lane] + a1 * ms[(j + 32) * 256 + f * 32 + lane];
    }
#pragma unroll
    for (int f = 0; f < 8; f++)
        retr[(size_t)m * 256 + f * 32 + lane] = tf32f(acc[f]);
}

// ---------------------------------------------------------------------------
// Final fused epilogue with NHWC->NCHW transpose
// ---------------------------------------------------------------------------
__global__ void k_final(const float* __restrict__ g, const float* __restrict__ retr,
                        const float* __restrict__ xf, const float* __restrict__ scv,
                        const float* __restrict__ scScale, const float* __restrict__ scShift,
                        float* __restrict__ out)
{
    __shared__ float tile[32][33];
    int b = blockIdx.x >> 5, p0 = (blockIdx.x & 31) << 5, c0 = blockIdx.y << 5;
    int tx = threadIdx.x, ty = threadIdx.y;
    for (int i = ty; i < 32; i += 8) {
        int m = (b << 10) + p0 + i;
        int c = c0 + tx;
        size_t id = (size_t)m * 256 + c;
        float gg = g[id], rr = retr[id], xx = xf[id];
        float mo = gg * rr + (1.f - gg) * xx;
        float spike = (0.1f * mo >= 1.f) ? 1.f : 0.f;
        float idn = scv[id] * scScale[c] + scShift[c];
        tile[tx][i] = fmaxf(spike + idn, 0.f);
    }
    __syncthreads();
    for (int i = ty; i < 32; i += 8)
        out[((size_t)b * 256 + c0 + i) * HWP + p0 + tx] = tile[i][tx];
}

// ---------------------------------------------------------------------------
// Launch
// ---------------------------------------------------------------------------
extern "C" void kernel_launch(void* const* d_in, const int* in_sizes, int n_in,
                              void* d_out, int out_size)
{
    const float* x        = (const float*)d_in[0];
    const float* conv1_w  = (const float*)d_in[1];
    const float* conv1_b  = (const float*)d_in[2];
    const float* bn1_g    = (const float*)d_in[3];
    const float* bn1_b    = (const float*)d_in[4];
    const float* conv2_w  = (const float*)d_in[5];
    const float* conv2_b  = (const float*)d_in[6];
    const float* bn2_g    = (const float*)d_in[7];
    const float* bn2_b    = (const float*)d_in[8];
    const float* ca_w1    = (const float*)d_in[9];
    const float* ca_w2    = (const float*)d_in[10];
    const float* sa_w     = (const float*)d_in[11];
    const float* sa_b     = (const float*)d_in[12];
    const float* memv     = (const float*)d_in[13];
    const float* mem_keys = (const float*)d_in[14];
    const float* ctrl_w1  = (const float*)d_in[15];
    const float* ctrl_b1  = (const float*)d_in[16];
    const float* ctrl_w2  = (const float*)d_in[17];
    const float* ctrl_b2  = (const float*)d_in[18];
    const float* gate_w   = (const float*)d_in[19];
    const float* gate_b   = (const float*)d_in[20];
    const float* sc_w     = (const float*)d_in[21];
    const float* sc_g     = (const float*)d_in[22];
    const float* sc_b     = (const float*)d_in[23];
    float* out = (float*)d_out;

    void* basep = nullptr;
    cudaGetSymbolAddress(&basep, g_scratch);
    float* S = (float*)basep;

    float* xn    = S + OFF_XN;
    float* t1    = S + OFF_T1;
    float* t2    = S + OFF_T2;
    float* xf    = S + OFF_XF;
    float* retr  = S + OFF_RETR;
    float* gate  = S + OFF_GATE;
    float* scv   = S + OFF_SCV;
    float* Lbuf  = S + OFF_L;
    float* w1r   = S + OFF_W1R;
    float* w2r   = S + OFF_W2R;
    float* w3r   = S + OFF_W3R;
    float* wgr   = S + OFF_WGR;
    float* wscr  = S + OFF_WSCR;
    float* KW    = S + OFF_KW;
    float* kb    = S + OFF_KB;
    float* psum  = S + OFF_PSUM;
    float* psq   = S + OFF_PSQ;
    float* pavg  = S + OFF_PAVG;
    float* pmax  = S + OFF_PMAX;
    float* catt  = S + OFF_CATT;
    float* spm   = S + OFF_SPM;
    float* spx   = S + OFF_SPX;
    float* sa    = S + OFF_SA;
    float* bn1sc = S + OFF_BN1SC;  float* bn1sh = S + OFF_BN1SH;
    float* bn2sc = S + OFF_BN2SC;  float* bn2sh = S + OFF_BN2SH;
    float* scsc  = S + OFF_SCSC;   float* scsh  = S + OFF_SCSH;

    const int dyn128 = 2 * (32 * 132 + 64 * 66) * 4;
    const int dyn64  = 2 * (32 * 132 + 32 * 66) * 4;
    cudaFuncSetAttribute(k_mma<128>, cudaFuncAttributeMaxDynamicSharedMemorySize, dyn128);
    cudaFuncSetAttribute(k_mma<64>,  cudaFuncAttributeMaxDynamicSharedMemorySize, dyn64);
    cudaFuncSetAttribute(k_softmax_retrieve, cudaFuncAttributeMaxDynamicSharedMemorySize, 65536);

    dim3 tb32x8(32, 8);
    dim3 g2(MROWS / 128, 2);   // N=256 tiles
    dim3 g1(MROWS / 128, 1);   // N=64 tiles

    // 1) x -> NHWC (tf32-rounded)
    k_nchw_to_nhwc<<<dim3(BB * 32, CIN / 32), tb32x8>>>(x, xn, CIN);

    // 2) weight prep: reorders (rounded), plain roundings, key-fold
    k_reorder_w<<<(COUT * CIN * 9 + 255) / 256, 256>>>(conv1_w, w1r, CIN);
    k_reorder_w<<<(COUT * COUT * 9 + 255) / 256, 256>>>(conv2_w, w2r, COUT);
    k_round<<<(COUT * COUT) / 256, 256>>>(ctrl_w1, w3r, COUT * COUT);
    k_round<<<(COUT * 2 * COUT) / 256, 256>>>(gate_w, wgr, COUT * 2 * COUT);
    k_round<<<(COUT * CIN) / 256, 256>>>(sc_w, wscr, COUT * CIN);
    k_keyfold<<<MEMN, 256>>>(mem_keys, ctrl_w2, ctrl_b2, KW, kb);

    // 3) conv1: implicit im2col GEMM (+bias, tf32-rounded out) -> t1
    k_mma<128><<<g2, 256, dyn128>>>(xn, nullptr, 1 << 30, 0, 0, 7, nullptr, nullptr,
                                    w1r, 9 * CIN, t1, conv1_b,
                                    COUT, 9 * CIN, 1.f, F_BIAS | F_TF32);

    // 4) BN1 stats (application fused into conv2 A-loader)
    k_bn_partial<<<256, 256>>>(t1, psum, psq);
    k_bn_finalize<<<1, 256>>>(psum, psq, bn1_g, bn1_b, bn1sc, bn1sh);

    // 5) conv2: implicit im2col GEMM with fused BN1+ReLU (+bias) -> t2 (raw)
    k_mma<128><<<g2, 256, dyn128>>>(t1, nullptr, 1 << 30, 0, 0, 8, bn1sc, bn1sh,
                                    w2r, 9 * COUT, t2, conv2_b,
                                    COUT, 9 * COUT, 1.f, F_BIAS);

    // 6) BN2 stats (apply fused into downstream consumers)
    k_bn_partial<<<256, 256>>>(t2, psum, psq);
    k_bn_finalize<<<1, 256>>>(psum, psq, bn2_g, bn2_b, bn2sc, bn2sh);

    // 7) channel attention (BN2 fused)
    k_ca_pool_partial<<<BB * 8, 256>>>(t2, bn2sc, bn2sh, pavg, pmax);
    k_ca_mlp<<<BB, 256>>>(pavg, pmax, ca_w1, ca_w2, catt);

    // 8) spatial attention (BN2 fused) -> xf (rounded)
    k_sp_pool<<<MROWS / 8, 256>>>(t2, bn2sc, bn2sh, catt, spm, spx);
    k_sa_conv<<<BB, 256>>>(spm, spx, sa_w, sa_b, sa);
    k_apply_att<<<MROWS * 64 / 256, 256>>>(t2, bn2sc, bn2sh, catt, sa, xf);

    // 9) memory module
    //   h1 = relu(xf @ ctrl_w1^T + b1) -> t1 (rounded)
    k_mma<128><<<g2, 256, dyn128>>>(xf, nullptr, 1 << 30, COUT, 0, 0, nullptr, nullptr,
                                    w3r, COUT, t1, ctrl_b1,
                                    COUT, COUT, 1.f, F_BIAS | F_RELU | F_TF32);
    //   logits = (h1 @ KW^T + kb')/16  (q-GEMM folded into KW)
    k_mma<64><<<g1, 256, dyn64>>>(t1, nullptr, 1 << 30, COUT, 0, 0, nullptr, nullptr,
                                  KW, COUT, Lbuf, kb,
                                  MEMN, COUT, 1.f / 16.f, F_BIAS);
    k_softmax_retrieve<<<MROWS / 8, 256, 65536>>>(Lbuf, memv, retr);
    //   gate = sigmoid([xf | retr] @ gate_w^T + gb) — K-concat
    k_mma<128><<<g2, 256, dyn128>>>(xf, retr, COUT, COUT, COUT, 0, nullptr, nullptr,
                                    wgr, 2 * COUT, gate, gate_b,
                                    COUT, 2 * COUT, 1.f, F_BIAS | F_SIG);

    // 10) shortcut 1x1 conv + BN stats
    k_mma<128><<<g2, 256, dyn128>>>(xn, nullptr, 1 << 30, CIN, 0, 0, nullptr, nullptr,
                                    wscr, CIN, scv, nullptr,
                                    COUT, CIN, 1.f, 0);
    k_bn_partial<<<256, 256>>>(scv, psum, psq);
    k_bn_finalize<<<1, 256>>>(psum, psq, sc_g, sc_b, scsc, scsh);

    // 11) final fused epilogue
    k_final<<<dim3(BB * 32, COUT / 32), tb32x8>>>(gate, retr, xf, scv, scsc, scsh, out);
}